// round 17
// baseline (speedup 1.0000x reference)
#include <cuda_runtime.h>
#include <cstdint>
#include <cstddef>

#define SEQ  4096
#define HID  1024
#define G4   4096
#define NCTA 128
#define SCAN_THREADS 256

typedef unsigned long long ull;

// ---------------- persistent device scratch (static: allocation-free) ----------
__device__ float g_xg[(size_t)SEQ * G4];   // 64 MB: precomputed input-side gates

// Tagged h records, PADDED to de-hotspot L2: chunk k (16B = records for columns
// 2k, 2k+1) lives at its own 256-byte-aligned slot so the 512 chunks spread
// across all ~184 LTS slices (bit 8 of the address varies per chunk; bit 7 is
// transparent to the addr->LTS hash). The old packed layout put all records in
// 64 L2 lines -> poll sweeps were slice-bound (~480 cyc); this layout is
// chip-BW-bound (~170 cyc). 2 parities x 512 chunks x 256B = 256 KB.
__device__ __align__(256) uint4 g_hpad[2][512][16];

// ---------------- packed f32x2 helpers ----------------------------------------
__device__ __forceinline__ ull pk2(float x, float y) {
  ull r; asm("mov.b64 %0, {%1, %2};" : "=l"(r) : "f"(x), "f"(y)); return r;
}
__device__ __forceinline__ void upk2(ull v, float& x, float& y) {
  asm("mov.b64 {%0, %1}, %2;" : "=f"(x), "=f"(y) : "l"(v));
}
__device__ __forceinline__ void fma2(ull& d, ull a, ull b) {
  asm("fma.rn.f32x2 %0, %1, %2, %0;" : "+l"(d) : "l"(a), "l"(b));
}

__device__ __forceinline__ float sigm(float x) {
  return __fdividef(1.0f, 1.0f + __expf(-x));
}
__device__ __forceinline__ float tanh_(float x) {
  float e = __expf(2.0f * x);
  return 1.0f - __fdividef(2.0f, e + 1.0f);
}

// strong (L2-coherent) 16B load: returns 2 records (h,tag,h,tag)
__device__ __forceinline__ uint4 ld_rec2(const void* p) {
  uint4 v;
  asm volatile("ld.relaxed.gpu.global.v4.b32 {%0,%1,%2,%3}, [%4];"
               : "=r"(v.x), "=r"(v.y), "=r"(v.z), "=r"(v.w) : "l"(p) : "memory");
  return v;
}
// strong 8B store: one record (h, tag) — tag travels with the payload
__device__ __forceinline__ void st_rec(void* p, float h, unsigned tag) {
  asm volatile("st.relaxed.gpu.global.v2.b32 [%0], {%1,%2};"
               :: "l"(p), "r"(__float_as_uint(h)), "r"(tag) : "memory");
}

// ==============================================================================
// Kernel 1: xg[m][n] = sum_k emb[inputs[m]][k] * W_ih[n][k] + b_ih[n] + b_hh[n]
// 128x128 tile, BK=8, 256 threads, 8x8 micro-tile via fma.rn.f32x2.
// DOUBLE-BUFFERED smem: one __syncthreads per K-tile (measured -58us vs two).
// Block (0,0) also zeroes ALL h-record chunks (both parities) — mandatory per
// launch: stale tags from a previous graph replay would satisfy the waits.
// ==============================================================================
__global__ __launch_bounds__(256, 2) void xg_gemm(
    const int*   __restrict__ inputs,
    const float* __restrict__ emb,
    const float* __restrict__ Wih,
    const float* __restrict__ b_ih,
    const float* __restrict__ b_hh)
{
  if (blockIdx.x == 0 && blockIdx.y == 0) {
    uint4 z = make_uint4(0u, 0u, 0u, 0u);
    // zero only the live 16B of each 256B slot (first uint4) for both parities
    for (int i = threadIdx.x; i < 2 * 512; i += 256)
      g_hpad[i >> 9][i & 511][0] = z;
  }

  __shared__ __align__(16) float As[2][8][128];
  __shared__ __align__(16) float Bs[2][8][128];
  __shared__ int idx[128];

  const int tid = threadIdx.x;
  const int m0 = blockIdx.y << 7;
  const int n0 = blockIdx.x << 7;

  if (tid < 128) idx[tid] = inputs[m0 + tid];
  __syncthreads();

  const int lr = tid >> 1;           // 0..127 row for cooperative loads
  const int lk = (tid & 1) << 2;     // k offset 0 or 4
  const int tx = tid & 15;           // micro-tile col group
  const int ty = tid >> 4;           // micro-tile row group

  const float* aptr = emb + (size_t)idx[lr] * 1024 + lk;
  const float* bptr = Wih + (size_t)(n0 + lr) * 1024 + lk;

  ull acc2[8][4];
  #pragma unroll
  for (int i = 0; i < 8; ++i)
    #pragma unroll
    for (int p = 0; p < 4; ++p) acc2[i][p] = 0ULL;

  // prologue: tile 0 -> buffer 0
  {
    float4 av = *(const float4*)(aptr);
    float4 bv = *(const float4*)(bptr);
    As[0][lk + 0][lr] = av.x; As[0][lk + 1][lr] = av.y;
    As[0][lk + 2][lr] = av.z; As[0][lk + 3][lr] = av.w;
    Bs[0][lk + 0][lr] = bv.x; Bs[0][lk + 1][lr] = bv.y;
    Bs[0][lk + 2][lr] = bv.z; Bs[0][lk + 3][lr] = bv.w;
  }
  __syncthreads();

  for (int t = 0; t < 128; ++t) {
    const int cur = t & 1;
    const int nxt = cur ^ 1;

    float4 av, bv;
    const bool has_next = (t + 1 < 128);
    if (has_next) {
      av = *(const float4*)(aptr + (t + 1) * 8);
      bv = *(const float4*)(bptr + (t + 1) * 8);
    }

    #pragma unroll
    for (int kk = 0; kk < 8; ++kk) {
      float4 a0 = *(const float4*)&As[cur][kk][ty << 3];
      float4 a1 = *(const float4*)&As[cur][kk][(ty << 3) + 4];
      float4 b0 = *(const float4*)&Bs[cur][kk][tx << 3];
      float4 b1 = *(const float4*)&Bs[cur][kk][(tx << 3) + 4];
      ull bq[4];
      bq[0] = pk2(b0.x, b0.y); bq[1] = pk2(b0.z, b0.w);
      bq[2] = pk2(b1.x, b1.y); bq[3] = pk2(b1.z, b1.w);
      float a[8] = {a0.x, a0.y, a0.z, a0.w, a1.x, a1.y, a1.z, a1.w};
      #pragma unroll
      for (int i = 0; i < 8; ++i) {
        ull ad = pk2(a[i], a[i]);
        #pragma unroll
        for (int p = 0; p < 4; ++p) fma2(acc2[i][p], ad, bq[p]);
      }
    }

    if (has_next) {
      As[nxt][lk + 0][lr] = av.x; As[nxt][lk + 1][lr] = av.y;
      As[nxt][lk + 2][lr] = av.z; As[nxt][lk + 3][lr] = av.w;
      Bs[nxt][lk + 0][lr] = bv.x; Bs[nxt][lk + 1][lr] = bv.y;
      Bs[nxt][lk + 2][lr] = bv.z; Bs[nxt][lk + 3][lr] = bv.w;
      __syncthreads();   // single barrier per tile
    }
  }

  float bias[8];
  #pragma unroll
  for (int p = 0; p < 8; ++p) {
    int n = n0 + (tx << 3) + p;
    bias[p] = b_ih[n] + b_hh[n];
  }
  #pragma unroll
  for (int i = 0; i < 8; ++i) {
    float c[8];
    #pragma unroll
    for (int p = 0; p < 4; ++p) upk2(acc2[i][p], c[2 * p], c[2 * p + 1]);
    #pragma unroll
    for (int p = 0; p < 8; ++p) c[p] += bias[p];
    int m = m0 + (ty << 3) + i;
    float* outp = g_xg + (size_t)m * G4 + n0 + (tx << 3);
    *(float4*)(outp)     = make_float4(c[0], c[1], c[2], c[3]);
    *(float4*)(outp + 4) = make_float4(c[4], c[5], c[6], c[7]);
  }
}

// ==============================================================================
// Kernel 2: persistent LSTM scan — frozen R7 protocol (two serial poll loops,
// tag+payload 8B records, per-warp publish, trailing barrier). The ONLY change
// vs the 6943us kernel is the record ADDRESSING: chunks padded to 256B slots
// so poll sweeps spread over all L2 slices instead of hammering 64 lines.
// 128 CTAs x 256 threads; CTA b owns h columns [8b, 8b+8), warp w -> column j.
// Thread tid owns columns 4tid..4tid+3 = chunks 2tid (cols 4tid,4tid+1) and
// 2tid+1 (cols 4tid+2,4tid+3).
// ==============================================================================
__global__ __launch_bounds__(SCAN_THREADS, 1) void lstm_scan(
    const float* __restrict__ W_hh,
    const float* __restrict__ h0,
    const float* __restrict__ c0)
{
  const int tid  = threadIdx.x;
  const int lane = tid & 31;
  const int w    = tid >> 5;                  // warp 0..7
  const int j    = (blockIdx.x << 3) + w;     // 0..1023

  __shared__ __align__(16) float sh_h[HID];

  // load this thread's 128 weights (as 64 f32x2 pairs) into registers
  ull wreg[4][16];
  #pragma unroll
  for (int g = 0; g < 4; ++g) {
    const float* wp = W_hh + (size_t)(j + (g << 10)) * HID;
    #pragma unroll
    for (int i = 0; i < 16; ++i) {
      float2 v = *(const float2*)(wp + 2 * (lane + 32 * i));
      wreg[g][i] = pk2(v.x, v.y);
    }
  }
  float c = c0[j];   // replicated across lanes (identical updates keep it consistent)

  for (int t = 0; t < SEQ; ++t) {
    // prefetch this step's input-side gate values early (hides DRAM/L2 latency
    // behind the record wait)
    float xgv = 0.0f;
    if (lane < 4) xgv = __ldg(g_xg + (size_t)t * G4 + j + (lane << 10));

    // --- obtain h_t into shared memory ---
    if (t == 0) {
      ((float4*)sh_h)[tid] = ((const float4*)h0)[tid];
    } else {
      // thread tid polls chunks 2tid and 2tid+1 (each its own 256B slot).
      // A 16B strong load returns (h,tag,h,tag) atomically: once tags >= t,
      // the h payloads in the same load are the current step's values.
      const uint4* rp0 = &g_hpad[t & 1][2 * tid][0];
      const uint4* rp1 = &g_hpad[t & 1][2 * tid + 1][0];
      const unsigned tt = (unsigned)t;
      uint4 a, b;
      do { a = ld_rec2(rp0); } while (a.y < tt || a.w < tt);
      do { b = ld_rec2(rp1); } while (b.y < tt || b.w < tt);
      ((float4*)sh_h)[tid] = make_float4(__uint_as_float(a.x), __uint_as_float(a.z),
                                         __uint_as_float(b.x), __uint_as_float(b.z));
    }
    __syncthreads();

    // --- 4 dot products of length 1024, f32x2 packed ---
    ull acc2[4];
    #pragma unroll
    for (int g = 0; g < 4; ++g) acc2[g] = 0ULL;
    #pragma unroll
    for (int i = 0; i < 16; ++i) {
      ull hh = *(const ull*)(sh_h + 2 * (lane + 32 * i));
      #pragma unroll
      for (int g = 0; g < 4; ++g) fma2(acc2[g], wreg[g][i], hh);
    }
    float acc[4];
    #pragma unroll
    for (int g = 0; g < 4; ++g) {
      float lo, hi; upk2(acc2[g], lo, hi);
      acc[g] = lo + hi;
    }
    // butterfly reduce: every lane ends with the full sums
    #pragma unroll
    for (int off = 16; off > 0; off >>= 1)
      #pragma unroll
      for (int g = 0; g < 4; ++g)
        acc[g] += __shfl_xor_sync(0xffffffffu, acc[g], off);

    float xg0 = __shfl_sync(0xffffffffu, xgv, 0);
    float xg1 = __shfl_sync(0xffffffffu, xgv, 1);
    float xg2 = __shfl_sync(0xffffffffu, xgv, 2);
    float xg3 = __shfl_sync(0xffffffffu, xgv, 3);

    // gate order i, f, g, o (PyTorch)
    float iv = sigm(acc[0] + xg0);
    float fv = sigm(acc[1] + xg1);
    float gv = tanh_(acc[2] + xg2);
    float ov = sigm(acc[3] + xg3);
    c = fv * c + iv * gv;
    float hn = ov * tanh_(c);

    // publish immediately — per-warp: column j -> chunk j>>1, record j&1
    if (lane == 0)
      st_rec((uint2*)&g_hpad[(t + 1) & 1][j >> 1][0] + (j & 1),
             hn, (unsigned)(t + 1));

    // protect sh_h against next step's overwrite while other warps still read it
    __syncthreads();
  }
}

// ==============================================================================
// Kernel 3: log_softmax over the final hidden state. After step t=4095 the
// final h was published with tag 4096 into parity-0 chunks. One CTA, 1024 thr.
// ==============================================================================
__global__ void lsm_kernel(float* __restrict__ out)
{
  const int tid  = threadIdx.x;
  const int lane = tid & 31;
  const int w    = tid >> 5;
  __shared__ float red[32];
  __shared__ float bcast[2];

  uint2 rec = ((const uint2*)&g_hpad[0][tid >> 1][0])[tid & 1];
  float v = __uint_as_float(rec.x);

  float m = v;
  #pragma unroll
  for (int o = 16; o > 0; o >>= 1) m = fmaxf(m, __shfl_xor_sync(0xffffffffu, m, o));
  if (lane == 0) red[w] = m;
  __syncthreads();
  if (tid < 32) {
    float x = red[tid];
    #pragma unroll
    for (int o = 16; o > 0; o >>= 1) x = fmaxf(x, __shfl_xor_sync(0xffffffffu, x, o));
    if (tid == 0) bcast[0] = x;
  }
  __syncthreads();
  m = bcast[0];

  float e = __expf(v - m);
  float s = e;
  #pragma unroll
  for (int o = 16; o > 0; o >>= 1) s += __shfl_xor_sync(0xffffffffu, s, o);
  if (lane == 0) red[w] = s;
  __syncthreads();
  if (tid < 32) {
    float x = red[tid];
    #pragma unroll
    for (int o = 16; o > 0; o >>= 1) x += __shfl_xor_sync(0xffffffffu, x, o);
    if (tid == 0) bcast[1] = logf(x);
  }
  __syncthreads();

  out[tid] = (v - m) - bcast[1];
}

// ==============================================================================
extern "C" void kernel_launch(void* const* d_in, const int* in_sizes, int n_in,
                              void* d_out, int out_size)
{
  const int*   inputs = (const int*)  d_in[0];
  const float* emb    = (const float*)d_in[1];
  const float* W_ih   = (const float*)d_in[2];
  const float* W_hh   = (const float*)d_in[3];
  const float* b_ih   = (const float*)d_in[4];
  const float* b_hh   = (const float*)d_in[5];
  const float* h0     = (const float*)d_in[6];
  const float* c0     = (const float*)d_in[7];
  float* out = (float*)d_out;

  dim3 grid(G4 / 128, SEQ / 128);
  xg_gemm<<<grid, 256>>>(inputs, emb, W_ih, b_ih, b_hh);
  lstm_scan<<<NCTA, SCAN_THREADS>>>(W_hh, h0, c0);
  lsm_kernel<<<1, HID>>>(out);
}